// round 9
// baseline (speedup 1.0000x reference)
#include <cuda_runtime.h>
#include <cuda_fp16.h>
#include <cstdint>

#define BB 8
#define TT 4096
#define DD 1024
#define HH 1024
#define MM (BB*TT)          // 32768 rows
#define NCHUNK 16
#define CHLEN (TT/NCHUNK)   // 256

// GEMM tiling: CTA 256(M) x 128(N = 64 z-cols + 64 h-cols), 8 consumer warps
#define CTA_M 256
#define KCH 64
#define NKT (DD/KCH)        // 16
#define STAGES 3
#define ROWB 144                                // 128B data + 16B pad
#define A_BYTES (CTA_M*ROWB)                    // 36864
#define B_BYTES (128*ROWB)                      // 18432
#define STAGE_BYTES (A_BYTES + B_BYTES)         // 55296
#define BAR_BYTES 64
#define SMEM_BYTES (STAGES*STAGE_BYTES + BAR_BYTES)  // 165952
#define EPI_STRIDE 132

// ---------------- scratch ---------------------------------------------------
__device__ __half g_X16[(size_t)MM*DD];          // x in fp16
__device__ __half g_WH [(size_t)2048*DD];        // interleaved [Wz^T|Wh^T] fp16
__device__ float2 g_ZV[(size_t)MM*HH];           // {1-z, z*g}
__device__ float  g_H [(size_t)MM*HH];
__device__ float  g_SA[BB*NCHUNK*HH];
__device__ float  g_SB[BB*NCHUNK*HH];
__device__ float  g_P [BB*NCHUNK*HH];

// ---------------- helpers ---------------------------------------------------
__device__ __forceinline__ void cp16(void* dst, const void* src) {
    uint32_t d = (uint32_t)__cvta_generic_to_shared(dst);
    asm volatile("cp.async.cg.shared.global [%0], [%1], 16;" :: "r"(d), "l"(src));
}

#define MBAR_INIT(addr, cnt) \
    asm volatile("mbarrier.init.shared.b64 [%0], %1;" :: "r"(addr), "r"(cnt) : "memory")
#define MBAR_ARRIVE(addr) \
    asm volatile("mbarrier.arrive.shared.b64 _, [%0];" :: "r"(addr) : "memory")
#define MBAR_WAIT(addr, parity) do {                                          \
    uint32_t _mb = (addr); uint32_t _p = (parity); uint32_t _done;            \
    asm volatile("{\n\t.reg .pred p;\n\t"                                     \
        "mbarrier.try_wait.parity.acquire.cta.shared::cta.b64 p, [%1], %2;\n\t" \
        "selp.b32 %0, 1, 0, p;\n\t}" : "=r"(_done) : "r"(_mb), "r"(_p) : "memory"); \
    if (!_done) {                                                             \
        asm volatile("{\n\t.reg .pred P1;\n\t"                                \
            "WL_%=:\n\t"                                                      \
            "mbarrier.try_wait.parity.acquire.cta.shared::cta.b64 P1, [%0], %1, 0x989680;\n\t" \
            "@P1 bra.uni WD_%=;\n\t"                                          \
            "bra.uni WL_%=;\n\t"                                              \
            "WD_%=:\n\t}" :: "r"(_mb), "r"(_p) : "memory");                   \
    }                                                                         \
} while (0)
#define CP_ASYNC_ARRIVE_NOINC(addr) \
    asm volatile("cp.async.mbarrier.arrive.noinc.shared.b64 [%0];" :: "r"(addr) : "memory")

__device__ __forceinline__ void mma16816(float* c, uint32_t a0, uint32_t a1,
                                         uint32_t a2, uint32_t a3,
                                         uint32_t b0, uint32_t b1) {
    asm volatile("mma.sync.aligned.m16n8k16.row.col.f32.f16.f16.f32 "
                 "{%0,%1,%2,%3}, {%4,%5,%6,%7}, {%8,%9}, {%0,%1,%2,%3};\n"
                 : "+f"(c[0]), "+f"(c[1]), "+f"(c[2]), "+f"(c[3])
                 : "r"(a0), "r"(a1), "r"(a2), "r"(a3), "r"(b0), "r"(b1));
}
__device__ __forceinline__ void ldsm4(uint32_t& r0, uint32_t& r1, uint32_t& r2,
                                      uint32_t& r3, uint32_t saddr) {
    asm volatile("ldmatrix.sync.aligned.m8n8.x4.shared.b16 {%0,%1,%2,%3}, [%4];"
                 : "=r"(r0), "=r"(r1), "=r"(r2), "=r"(r3) : "r"(saddr));
}

// ---------------- prep: x -> fp16 -------------------------------------------
__global__ __launch_bounds__(256)
void prep_x_kernel(const float* __restrict__ x) {
    size_t i = (size_t)blockIdx.x * blockDim.x + threadIdx.x;   // one float4
    float4 v = ((const float4*)x)[i];
    ((__half2*)g_X16)[2*i]   = __half2(__float2half(v.x), __float2half(v.y));
    ((__half2*)g_X16)[2*i+1] = __half2(__float2half(v.z), __float2half(v.w));
}

// ---------------- prep: W[k][h] -> interleaved WT rows ----------------------
__global__ __launch_bounds__(256)
void prep_w_kernel(const float* __restrict__ W, int is_h) {
    __shared__ float tile[32][33];
    const int k0 = blockIdx.x * 32, h0 = blockIdx.y * 32;
    #pragma unroll
    for (int j = 0; j < 4; j++) {
        int kk = threadIdx.y * 4 + j;
        tile[kk][threadIdx.x] = W[(size_t)(k0 + kk) * HH + h0 + threadIdx.x];
    }
    __syncthreads();
    #pragma unroll
    for (int j = 0; j < 4; j++) {
        int h = h0 + threadIdx.y * 4 + j;
        float val = tile[threadIdx.x][threadIdx.y * 4 + j];
        int orow = (h >> 6) * 128 + (is_h ? 64 : 0) + (h & 63);
        g_WH[(size_t)orow * DD + k0 + threadIdx.x] = __float2half(val);
    }
}

// ---------------- GEMM: warp-specialized mbarrier pipeline ------------------
__global__ __launch_bounds__(288, 1)
void gemm_kernel(const float* __restrict__ bz, const float* __restrict__ bh) {
    extern __shared__ char smem[];
    const int tid  = threadIdx.x;
    const int wid  = tid >> 5;
    const int lane = tid & 31;
    const int nb = blockIdx.x;          // 0..15
    const int m0 = blockIdx.y * CTA_M;
    const int h0 = nb * 64;

    const uint32_t sbase = (uint32_t)__cvta_generic_to_shared(smem);
    const uint32_t barB  = sbase + STAGES * STAGE_BYTES;
    // full[s] = barB + s*8 (count 32); empty[s] = barB + 24 + s*8 (count 8)

    if (tid == 0) {
        #pragma unroll
        for (int s = 0; s < STAGES; s++) {
            MBAR_INIT(barB + s * 8, 32);
            MBAR_INIT(barB + 24 + s * 8, 8);
        }
    }
    __syncthreads();

    float acc[4][8][4];

    if (wid < 8) {
        // ======== consumers ========
        const int wm = wid >> 1;            // 0..3 -> M offset wm*64
        const int wn = wid & 1;             // 0..1 -> B-row offset wn*64
        #pragma unroll
        for (int mi = 0; mi < 4; mi++)
            #pragma unroll
            for (int ni = 0; ni < 8; ni++)
                #pragma unroll
                for (int j = 0; j < 4; j++) acc[mi][ni][j] = 0.f;

        const int g = lane >> 3, l = lane & 7;
        const uint32_t aoff = (uint32_t)((wm * 64 + (g & 1) * 8 + l) * ROWB + (g >> 1) * 16);
        const uint32_t boff = (uint32_t)((wn * 64 + (g >> 1) * 8 + l) * ROWB + (g & 1) * 16);

        uint32_t af[2][4][4];
        uint32_t bf[2][8][2];

        #pragma unroll 1
        for (int kt = 0; kt < NKT; kt++) {
            const int s = kt % STAGES;
            MBAR_WAIT(barB + s * 8, (kt / STAGES) & 1);

            const uint32_t stg = sbase + s * STAGE_BYTES;
            const uint32_t Ab = stg + aoff;
            const uint32_t Bb = stg + A_BYTES + boff;

            #pragma unroll
            for (int mi = 0; mi < 4; mi++)
                ldsm4(af[0][mi][0], af[0][mi][1], af[0][mi][2], af[0][mi][3],
                      Ab + mi * 16 * ROWB);
            #pragma unroll
            for (int p = 0; p < 4; p++)
                ldsm4(bf[0][2*p][0], bf[0][2*p][1], bf[0][2*p+1][0], bf[0][2*p+1][1],
                      Bb + p * 16 * ROWB);

            #pragma unroll
            for (int kk = 0; kk < 4; kk++) {
                const int cur = kk & 1, nxt = cur ^ 1;
                if (kk < 3) {
                    const uint32_t kb = (kk + 1) * 32;
                    #pragma unroll
                    for (int mi = 0; mi < 4; mi++)
                        ldsm4(af[nxt][mi][0], af[nxt][mi][1], af[nxt][mi][2], af[nxt][mi][3],
                              Ab + kb + mi * 16 * ROWB);
                    #pragma unroll
                    for (int p = 0; p < 4; p++)
                        ldsm4(bf[nxt][2*p][0], bf[nxt][2*p][1], bf[nxt][2*p+1][0], bf[nxt][2*p+1][1],
                              Bb + kb + p * 16 * ROWB);
                }
                #pragma unroll
                for (int mi = 0; mi < 4; mi++)
                    #pragma unroll
                    for (int ni = 0; ni < 8; ni++)
                        mma16816(acc[mi][ni], af[cur][mi][0], af[cur][mi][1],
                                 af[cur][mi][2], af[cur][mi][3],
                                 bf[cur][ni][0], bf[cur][ni][1]);
            }
            __syncwarp();
            if (lane == 0) MBAR_ARRIVE(barB + 24 + s * 8);
        }
    } else {
        // ======== producer warp (wid == 8) ========
        const __half* gA = g_X16 + (size_t)m0 * DD;
        const __half* gB = g_WH + (size_t)nb * 128 * DD;
        #pragma unroll 1
        for (int kt = 0; kt < NKT; kt++) {
            const int s = kt % STAGES;
            if (kt >= STAGES) MBAR_WAIT(barB + 24 + s * 8, ((kt / STAGES) - 1) & 1);
            char* stg = smem + s * STAGE_BYTES;
            const int k0 = kt * KCH;
            #pragma unroll 4
            for (int i = 0; i < 96; i++) {      // 96*32 = 3072 chunks exactly
                int q = lane + i * 32;          // 0..3071
                if (q < 2048) {                 // A: 256 rows x 8 chunks
                    int row = q >> 3, c = q & 7;
                    cp16(stg + row * ROWB + c * 16, gA + (size_t)row * DD + k0 + c * 8);
                } else {                        // B: 128 rows x 8 chunks
                    int q2 = q - 2048, row = q2 >> 3, c = q2 & 7;
                    cp16(stg + A_BYTES + row * ROWB + c * 16, gB + (size_t)row * DD + k0 + c * 8);
                }
            }
            CP_ASYNC_ARRIVE_NOINC(barB + s * 8);
        }
    }

    __syncthreads();

    // ---- epilogue: stage accums through smem, fuse activations ----
    float* epi = (float*)smem;   // [256][EPI_STRIDE]
    if (wid < 8) {
        const int wm = wid >> 1, wn = wid & 1;
        #pragma unroll
        for (int mi = 0; mi < 4; mi++) {
            #pragma unroll
            for (int ni = 0; ni < 8; ni++) {
                int r0 = wm * 64 + mi * 16 + (lane >> 2);
                int c0 = wn * 64 + ni * 8 + (lane & 3) * 2;
                *(float2*)&epi[(size_t)r0 * EPI_STRIDE + c0] = make_float2(acc[mi][ni][0], acc[mi][ni][1]);
                *(float2*)&epi[(size_t)(r0 + 8) * EPI_STRIDE + c0] = make_float2(acc[mi][ni][2], acc[mi][ni][3]);
            }
        }
    }
    __syncthreads();

    if (tid < 256) {
        const int r = tid;   // 0..255
        const size_t zvbase = (size_t)(m0 + r) * HH + h0;
        #pragma unroll 4
        for (int c = 0; c < 64; c += 2) {
            float k0v = epi[(size_t)r * EPI_STRIDE + c]     + __ldg(&bz[h0 + c]);
            float k1v = epi[(size_t)r * EPI_STRIDE + c + 1] + __ldg(&bz[h0 + c + 1]);
            float a0v = epi[(size_t)r * EPI_STRIDE + 64 + c]     + __ldg(&bh[h0 + c]);
            float a1v = epi[(size_t)r * EPI_STRIDE + 64 + c + 1] + __ldg(&bh[h0 + c + 1]);
            float e0 = __expf(-k0v), e1 = __expf(-k1v);
            float i0 = __fdividef(1.f, 1.f + e0), i1 = __fdividef(1.f, 1.f + e1);
            float om0 = e0 * i0, om1 = e1 * i1;           // 1 - z
            float g0 = (a0v >= 0.f) ? (a0v + 0.5f) : __fdividef(1.f, 1.f + __expf(-a0v));
            float g1 = (a1v >= 0.f) ? (a1v + 0.5f) : __fdividef(1.f, 1.f + __expf(-a1v));
            *(float4*)&g_ZV[zvbase + c] = make_float4(om0, i0 * g0, om1, i1 * g1);
        }
    }
}

// ---------------- scan kernels ---------------------------------------------
__global__ __launch_bounds__(128)
void scan_summary_kernel() {
    const int ch = blockIdx.x * 128 + threadIdx.x;
    const int c  = blockIdx.y;
    const int b  = blockIdx.z;
    size_t base = ((size_t)b * TT + (size_t)c * CHLEN) * HH + ch;
    float Aacc = 1.f, Bacc = 0.f;
    #pragma unroll 8
    for (int t = 0; t < CHLEN; ++t) {
        const float2 zv = __ldg(&g_ZV[base]);
        Aacc *= zv.x;
        Bacc = fmaf(zv.x, Bacc, zv.y);
        base += HH;
    }
    const int s = (b * NCHUNK + c) * HH + ch;
    g_SA[s] = Aacc;
    g_SB[s] = Bacc;
}

__global__ __launch_bounds__(256)
void scan_prefix_kernel(float* __restrict__ hidden) {
    const int idx = blockIdx.x * blockDim.x + threadIdx.x;
    const int b  = idx / HH;
    const int ch = idx - b * HH;
    float h = 0.f;
    #pragma unroll
    for (int c = 0; c < NCHUNK; ++c) {
        const int s = (b * NCHUNK + c) * HH + ch;
        g_P[s] = h;
        h = fmaf(g_SA[s], h, g_SB[s]);
    }
    if (hidden) hidden[(size_t)b * HH + ch] = h;
}

__global__ __launch_bounds__(128)
void scan_final_kernel() {
    const int ch = blockIdx.x * 128 + threadIdx.x;
    const int c  = blockIdx.y;
    const int b  = blockIdx.z;
    size_t base = ((size_t)b * TT + (size_t)c * CHLEN) * HH + ch;
    float h = g_P[(b * NCHUNK + c) * HH + ch];
    #pragma unroll 8
    for (int t = 0; t < CHLEN; ++t) {
        const float2 zv = __ldg(&g_ZV[base]);
        h = fmaf(zv.x, h, zv.y);
        g_H[base] = h;
        base += HH;
    }
}

// ---------------- LayerNorm + residual -------------------------------------
__global__ __launch_bounds__(256)
void ln_residual_kernel(const float* __restrict__ x,
                        const float* __restrict__ gamma,
                        const float* __restrict__ beta,
                        float* __restrict__ out)
{
    __shared__ float sm[8];
    const int row = blockIdx.x;
    const int c   = threadIdx.x * 4;
    const size_t off = (size_t)row * HH + c;

    float4 h4 = *(const float4*)&g_H[off];
    float s = h4.x + h4.y + h4.z + h4.w;
    #pragma unroll
    for (int o = 16; o > 0; o >>= 1) s += __shfl_xor_sync(0xffffffffu, s, o);
    if ((threadIdx.x & 31) == 0) sm[threadIdx.x >> 5] = s;
    __syncthreads();
    const float mean = (sm[0]+sm[1]+sm[2]+sm[3]+sm[4]+sm[5]+sm[6]+sm[7]) * (1.f/HH);
    __syncthreads();

    const float dx = h4.x - mean, dy = h4.y - mean, dz = h4.z - mean, dw = h4.w - mean;
    float ss = dx*dx + dy*dy + dz*dz + dw*dw;
    #pragma unroll
    for (int o = 16; o > 0; o >>= 1) ss += __shfl_xor_sync(0xffffffffu, ss, o);
    if ((threadIdx.x & 31) == 0) sm[threadIdx.x >> 5] = ss;
    __syncthreads();
    const float var  = (sm[0]+sm[1]+sm[2]+sm[3]+sm[4]+sm[5]+sm[6]+sm[7]) * (1.f/HH);
    const float rstd = rsqrtf(var + 1e-5f);

    float4 xv = *(const float4*)&x[off];
    float4 gv = *(const float4*)&gamma[c];
    float4 bv = *(const float4*)&beta[c];
    float4 o4;
    o4.x = dx * rstd * gv.x + bv.x + xv.x;
    o4.y = dy * rstd * gv.y + bv.y + xv.y;
    o4.z = dz * rstd * gv.z + bv.z + xv.z;
    o4.w = dw * rstd * gv.w + bv.w + xv.w;
    *(float4*)&out[off] = o4;
}

// ---------------------------------------------------------------------------
extern "C" void kernel_launch(void* const* d_in, const int* in_sizes, int n_in,
                              void* d_out, int out_size)
{
    const float* x     = (const float*)d_in[0];
    const float* Wz    = (const float*)d_in[1];
    const float* bz    = (const float*)d_in[2];
    const float* Wh    = (const float*)d_in[3];
    const float* bh    = (const float*)d_in[4];
    const float* gamma = (const float*)d_in[5];
    const float* beta  = (const float*)d_in[6];
    float* out = (float*)d_out;

    float* hidden = nullptr;
    if ((long long)out_size >= (long long)MM * HH + (long long)BB * HH)
        hidden = out + (size_t)MM * HH;

    static bool attr_set = false;
    if (!attr_set) {
        cudaFuncSetAttribute(gemm_kernel, cudaFuncAttributeMaxDynamicSharedMemorySize, SMEM_BYTES);
        attr_set = true;
    }

    prep_x_kernel<<<(MM * DD / 4) / 256, 256>>>(x);
    prep_w_kernel<<<dim3(DD/32, HH/32), dim3(32, 8)>>>(Wz, 0);
    prep_w_kernel<<<dim3(DD/32, HH/32), dim3(32, 8)>>>(Wh, 1);
    gemm_kernel<<<dim3(HH/64, MM/CTA_M), 288, SMEM_BYTES>>>(bz, bh);
    scan_summary_kernel<<<dim3(HH/128, NCHUNK, BB), 128>>>();
    scan_prefix_kernel<<<(BB*HH)/256, 256>>>(hidden);
    scan_final_kernel<<<dim3(HH/128, NCHUNK, BB), 128>>>();
    ln_residual_kernel<<<MM, 256>>>(x, gamma, beta, out);
}

// round 12
// speedup vs baseline: 1.0709x; 1.0709x over previous
#include <cuda_runtime.h>
#include <cuda_fp16.h>
#include <cstdint>

#define BB 8
#define TT 4096
#define DD 1024
#define HH 1024
#define MM (BB*TT)          // 32768 rows
#define NCHUNK 16
#define CHLEN (TT/NCHUNK)   // 256

// GEMM tiling: CTA 256(M) x 128(N = 64 z-cols + 64 h-cols), 8 warps
#define CTA_M 256
#define KCH 64
#define NKT (DD/KCH)        // 16
#define STAGES 3
#define ROWB 144                                // 128B data + 16B pad
#define A_BYTES (CTA_M*ROWB)                    // 36864
#define B_BYTES (128*ROWB)                      // 18432
#define STAGE_BYTES (A_BYTES + B_BYTES)         // 55296
#define BAR_BYTES 64
#define SMEM_BYTES (STAGES*STAGE_BYTES + BAR_BYTES)  // 165952
#define EPI_STRIDE 132

// ---------------- scratch ---------------------------------------------------
__device__ __half g_X16[(size_t)MM*DD];          // x in fp16
__device__ __half g_WH [(size_t)2048*DD];        // interleaved [Wz^T|Wh^T] fp16
__device__ float2 g_ZV[(size_t)MM*HH];           // {1-z, z*g}
__device__ float  g_H [(size_t)MM*HH];
__device__ float  g_SA[BB*NCHUNK*HH];
__device__ float  g_SB[BB*NCHUNK*HH];
__device__ float  g_P [BB*NCHUNK*HH];

// ---------------- helpers ---------------------------------------------------
__device__ __forceinline__ void cp16(void* dst, const void* src) {
    uint32_t d = (uint32_t)__cvta_generic_to_shared(dst);
    asm volatile("cp.async.cg.shared.global [%0], [%1], 16;" :: "r"(d), "l"(src));
}
__device__ __forceinline__ void cp_commit() { asm volatile("cp.async.commit_group;"); }

#define MBAR_INIT(addr, cnt) \
    asm volatile("mbarrier.init.shared.b64 [%0], %1;" :: "r"(addr), "r"(cnt) : "memory")
#define MBAR_ARRIVE(addr) \
    asm volatile("mbarrier.arrive.shared.b64 _, [%0];" :: "r"(addr) : "memory")
#define MBAR_WAIT(addr, parity) do {                                          \
    uint32_t _mb = (addr); uint32_t _p = (parity); uint32_t _done;            \
    asm volatile("{\n\t.reg .pred p;\n\t"                                     \
        "mbarrier.try_wait.parity.acquire.cta.shared::cta.b64 p, [%1], %2;\n\t" \
        "selp.b32 %0, 1, 0, p;\n\t}" : "=r"(_done) : "r"(_mb), "r"(_p) : "memory"); \
    if (!_done) {                                                             \
        asm volatile("{\n\t.reg .pred P1;\n\t"                                \
            "WL_%=:\n\t"                                                      \
            "mbarrier.try_wait.parity.acquire.cta.shared::cta.b64 P1, [%0], %1, 0x989680;\n\t" \
            "@P1 bra.uni WD_%=;\n\t"                                          \
            "bra.uni WL_%=;\n\t"                                              \
            "WD_%=:\n\t}" :: "r"(_mb), "r"(_p) : "memory");                   \
    }                                                                         \
} while (0)

__device__ __forceinline__ void mma16816(float* c, uint32_t a0, uint32_t a1,
                                         uint32_t a2, uint32_t a3,
                                         uint32_t b0, uint32_t b1) {
    asm volatile("mma.sync.aligned.m16n8k16.row.col.f32.f16.f16.f32 "
                 "{%0,%1,%2,%3}, {%4,%5,%6,%7}, {%8,%9}, {%0,%1,%2,%3};\n"
                 : "+f"(c[0]), "+f"(c[1]), "+f"(c[2]), "+f"(c[3])
                 : "r"(a0), "r"(a1), "r"(a2), "r"(a3), "r"(b0), "r"(b1));
}
__device__ __forceinline__ void ldsm4(uint32_t& r0, uint32_t& r1, uint32_t& r2,
                                      uint32_t& r3, uint32_t saddr) {
    asm volatile("ldmatrix.sync.aligned.m8n8.x4.shared.b16 {%0,%1,%2,%3}, [%4];"
                 : "=r"(r0), "=r"(r1), "=r"(r2), "=r"(r3) : "r"(saddr));
}

// ---------------- prep: x -> fp16 -------------------------------------------
__global__ __launch_bounds__(256)
void prep_x_kernel(const float* __restrict__ x) {
    size_t i = (size_t)blockIdx.x * blockDim.x + threadIdx.x;   // one float4
    float4 v = ((const float4*)x)[i];
    ((__half2*)g_X16)[2*i]   = __half2(__float2half(v.x), __float2half(v.y));
    ((__half2*)g_X16)[2*i+1] = __half2(__float2half(v.z), __float2half(v.w));
}

// ---------------- prep: W[k][h] -> interleaved WT rows ----------------------
__global__ __launch_bounds__(256)
void prep_w_kernel(const float* __restrict__ W, int is_h) {
    __shared__ float tile[32][33];
    const int k0 = blockIdx.x * 32, h0 = blockIdx.y * 32;
    #pragma unroll
    for (int j = 0; j < 4; j++) {
        int kk = threadIdx.y * 4 + j;
        tile[kk][threadIdx.x] = W[(size_t)(k0 + kk) * HH + h0 + threadIdx.x];
    }
    __syncthreads();
    #pragma unroll
    for (int j = 0; j < 4; j++) {
        int h = h0 + threadIdx.y * 4 + j;
        float val = tile[threadIdx.x][threadIdx.y * 4 + j];
        int orow = (h >> 6) * 128 + (is_h ? 64 : 0) + (h & 63);
        g_WH[(size_t)orow * DD + k0 + threadIdx.x] = __float2half(val);
    }
}

// ---------------- GEMM: split arrive/wait pipeline (proven primitives only) -
// Each warp loads its 1/8 of every stage; own-group completion confirmed via
// cp.async.wait_group, stage readiness via count-8 mbarrier (one arrive/warp).
__device__ __forceinline__ void load_share(char* stg, int k0, int wid, int lane,
                                           const __half* gA, const __half* gB) {
    #pragma unroll
    for (int i = 0; i < 12; i++) {
        int q = wid * 384 + lane + i * 32;   // this warp's 384 of 3072 chunks
        if (q < 2048) {                      // A: 256 rows x 8 chunks
            int row = q >> 3, c = q & 7;
            cp16(stg + row * ROWB + c * 16, gA + (size_t)row * DD + k0 + c * 8);
        } else {                             // B: 128 rows x 8 chunks
            int q2 = q - 2048, row = q2 >> 3, c = q2 & 7;
            cp16(stg + A_BYTES + row * ROWB + c * 16, gB + (size_t)row * DD + k0 + c * 8);
        }
    }
}

__global__ __launch_bounds__(256, 1)
void gemm_kernel(const float* __restrict__ bz, const float* __restrict__ bh) {
    extern __shared__ char smem[];
    const int tid  = threadIdx.x;
    const int wid  = tid >> 5;
    const int lane = tid & 31;
    const int nb = blockIdx.x;          // 0..15
    const int m0 = blockIdx.y * CTA_M;
    const int h0 = nb * 64;

    const uint32_t sbase = (uint32_t)__cvta_generic_to_shared(smem);
    const uint32_t barB  = sbase + STAGES * STAGE_BYTES;
    // full[s] = barB + s*8 (count 8); empty[s] = barB + 24 + s*8 (count 8)

    if (tid == 0) {
        #pragma unroll
        for (int s = 0; s < STAGES; s++) {
            MBAR_INIT(barB + s * 8, 8);
            MBAR_INIT(barB + 24 + s * 8, 8);
        }
    }
    __syncthreads();

    const int wm = wid >> 1;            // 0..3 -> M offset wm*64
    const int wn = wid & 1;             // 0..1 -> B-row offset wn*64

    float acc[4][8][4];
    #pragma unroll
    for (int mi = 0; mi < 4; mi++)
        #pragma unroll
        for (int ni = 0; ni < 8; ni++)
            #pragma unroll
            for (int j = 0; j < 4; j++) acc[mi][ni][j] = 0.f;

    const __half* gA = g_X16 + (size_t)m0 * DD;
    const __half* gB = g_WH + (size_t)nb * 128 * DD;

    // prologue: every warp loads its share of stages 0..1 (one group each)
    load_share(smem + 0 * STAGE_BYTES, 0 * KCH, wid, lane, gA, gB);
    cp_commit();
    load_share(smem + 1 * STAGE_BYTES, 1 * KCH, wid, lane, gA, gB);
    cp_commit();

    const int g = lane >> 3, l = lane & 7;
    const uint32_t aoff = (uint32_t)((wm * 64 + (g & 1) * 8 + l) * ROWB + (g >> 1) * 16);
    const uint32_t boff = (uint32_t)((wn * 64 + (g >> 1) * 8 + l) * ROWB + (g & 1) * 16);

    uint32_t af[2][4][4];
    uint32_t bf[2][8][2];

    #pragma unroll 1
    for (int kt = 0; kt < NKT; kt++) {
        const int s = kt % STAGES;

        // preload stage kt+2 (this warp's share), one commit group
        const int pl = kt + STAGES - 1;
        if (pl < NKT) {
            const int sp = pl % STAGES;
            if (pl >= STAGES) MBAR_WAIT(barB + 24 + sp * 8, ((pl / STAGES) - 1) & 1);
            load_share(smem + sp * STAGE_BYTES, pl * KCH, wid, lane, gA, gB);
            cp_commit();
        }

        // confirm OWN group for stage s landed, then signal this warp's share
        if (kt < NKT - 2)       asm volatile("cp.async.wait_group 2;" ::: "memory");
        else if (kt == NKT - 2) asm volatile("cp.async.wait_group 1;" ::: "memory");
        else                    asm volatile("cp.async.wait_group 0;" ::: "memory");
        __syncwarp();
        if (lane == 0) MBAR_ARRIVE(barB + s * 8);

        // wait until ALL warps' shares of stage s landed
        MBAR_WAIT(barB + s * 8, (kt / STAGES) & 1);

        const uint32_t stg = sbase + s * STAGE_BYTES;
        const uint32_t Ab = stg + aoff;
        const uint32_t Bb = stg + A_BYTES + boff;

        #pragma unroll
        for (int mi = 0; mi < 4; mi++)
            ldsm4(af[0][mi][0], af[0][mi][1], af[0][mi][2], af[0][mi][3],
                  Ab + mi * 16 * ROWB);
        #pragma unroll
        for (int p = 0; p < 4; p++)
            ldsm4(bf[0][2*p][0], bf[0][2*p][1], bf[0][2*p+1][0], bf[0][2*p+1][1],
                  Bb + p * 16 * ROWB);

        #pragma unroll
        for (int kk = 0; kk < 4; kk++) {
            const int cur = kk & 1, nxt = cur ^ 1;
            if (kk < 3) {
                const uint32_t kb = (kk + 1) * 32;
                #pragma unroll
                for (int mi = 0; mi < 4; mi++)
                    ldsm4(af[nxt][mi][0], af[nxt][mi][1], af[nxt][mi][2], af[nxt][mi][3],
                          Ab + kb + mi * 16 * ROWB);
                #pragma unroll
                for (int p = 0; p < 4; p++)
                    ldsm4(bf[nxt][2*p][0], bf[nxt][2*p][1], bf[nxt][2*p+1][0], bf[nxt][2*p+1][1],
                          Bb + kb + p * 16 * ROWB);
            }
            #pragma unroll
            for (int mi = 0; mi < 4; mi++)
                #pragma unroll
                for (int ni = 0; ni < 8; ni++)
                    mma16816(acc[mi][ni], af[cur][mi][0], af[cur][mi][1],
                             af[cur][mi][2], af[cur][mi][3],
                             bf[cur][ni][0], bf[cur][ni][1]);
        }
        __syncwarp();
        if (lane == 0) MBAR_ARRIVE(barB + 24 + s * 8);
    }
    __syncthreads();

    // ---- epilogue: stage accums through smem, fuse activations ----
    float* epi = (float*)smem;   // [256][EPI_STRIDE]
    #pragma unroll
    for (int mi = 0; mi < 4; mi++) {
        #pragma unroll
        for (int ni = 0; ni < 8; ni++) {
            int r0 = wm * 64 + mi * 16 + (lane >> 2);
            int c0 = wn * 64 + ni * 8 + (lane & 3) * 2;
            *(float2*)&epi[(size_t)r0 * EPI_STRIDE + c0] = make_float2(acc[mi][ni][0], acc[mi][ni][1]);
            *(float2*)&epi[(size_t)(r0 + 8) * EPI_STRIDE + c0] = make_float2(acc[mi][ni][2], acc[mi][ni][3]);
        }
    }
    __syncthreads();

    const int r = tid;   // 0..255
    const size_t zvbase = (size_t)(m0 + r) * HH + h0;
    #pragma unroll 4
    for (int c = 0; c < 64; c += 2) {
        float k0v = epi[(size_t)r * EPI_STRIDE + c]     + __ldg(&bz[h0 + c]);
        float k1v = epi[(size_t)r * EPI_STRIDE + c + 1] + __ldg(&bz[h0 + c + 1]);
        float a0v = epi[(size_t)r * EPI_STRIDE + 64 + c]     + __ldg(&bh[h0 + c]);
        float a1v = epi[(size_t)r * EPI_STRIDE + 64 + c + 1] + __ldg(&bh[h0 + c + 1]);
        float e0 = __expf(-k0v), e1 = __expf(-k1v);
        float i0 = __fdividef(1.f, 1.f + e0), i1 = __fdividef(1.f, 1.f + e1);
        float om0 = e0 * i0, om1 = e1 * i1;           // 1 - z
        float g0 = (a0v >= 0.f) ? (a0v + 0.5f) : __fdividef(1.f, 1.f + __expf(-a0v));
        float g1 = (a1v >= 0.f) ? (a1v + 0.5f) : __fdividef(1.f, 1.f + __expf(-a1v));
        *(float4*)&g_ZV[zvbase + c] = make_float4(om0, i0 * g0, om1, i1 * g1);
    }
}

// ---------------- scan kernels ---------------------------------------------
__global__ __launch_bounds__(128)
void scan_summary_kernel() {
    const int ch = blockIdx.x * 128 + threadIdx.x;
    const int c  = blockIdx.y;
    const int b  = blockIdx.z;
    size_t base = ((size_t)b * TT + (size_t)c * CHLEN) * HH + ch;
    float Aacc = 1.f, Bacc = 0.f;
    #pragma unroll 8
    for (int t = 0; t < CHLEN; ++t) {
        const float2 zv = __ldg(&g_ZV[base]);
        Aacc *= zv.x;
        Bacc = fmaf(zv.x, Bacc, zv.y);
        base += HH;
    }
    const int s = (b * NCHUNK + c) * HH + ch;
    g_SA[s] = Aacc;
    g_SB[s] = Bacc;
}

__global__ __launch_bounds__(256)
void scan_prefix_kernel(float* __restrict__ hidden) {
    const int idx = blockIdx.x * blockDim.x + threadIdx.x;
    const int b  = idx / HH;
    const int ch = idx - b * HH;
    float h = 0.f;
    #pragma unroll
    for (int c = 0; c < NCHUNK; ++c) {
        const int s = (b * NCHUNK + c) * HH + ch;
        g_P[s] = h;
        h = fmaf(g_SA[s], h, g_SB[s]);
    }
    if (hidden) hidden[(size_t)b * HH + ch] = h;
}

__global__ __launch_bounds__(128)
void scan_final_kernel() {
    const int ch = blockIdx.x * 128 + threadIdx.x;
    const int c  = blockIdx.y;
    const int b  = blockIdx.z;
    size_t base = ((size_t)b * TT + (size_t)c * CHLEN) * HH + ch;
    float h = g_P[(b * NCHUNK + c) * HH + ch];
    #pragma unroll 8
    for (int t = 0; t < CHLEN; ++t) {
        const float2 zv = __ldg(&g_ZV[base]);
        h = fmaf(zv.x, h, zv.y);
        g_H[base] = h;
        base += HH;
    }
}

// ---------------- LayerNorm + residual -------------------------------------
__global__ __launch_bounds__(256)
void ln_residual_kernel(const float* __restrict__ x,
                        const float* __restrict__ gamma,
                        const float* __restrict__ beta,
                        float* __restrict__ out)
{
    __shared__ float sm[8];
    const int row = blockIdx.x;
    const int c   = threadIdx.x * 4;
    const size_t off = (size_t)row * HH + c;

    float4 h4 = *(const float4*)&g_H[off];
    float s = h4.x + h4.y + h4.z + h4.w;
    #pragma unroll
    for (int o = 16; o > 0; o >>= 1) s += __shfl_xor_sync(0xffffffffu, s, o);
    if ((threadIdx.x & 31) == 0) sm[threadIdx.x >> 5] = s;
    __syncthreads();
    const float mean = (sm[0]+sm[1]+sm[2]+sm[3]+sm[4]+sm[5]+sm[6]+sm[7]) * (1.f/HH);
    __syncthreads();

    const float dx = h4.x - mean, dy = h4.y - mean, dz = h4.z - mean, dw = h4.w - mean;
    float ss = dx*dx + dy*dy + dz*dz + dw*dw;
    #pragma unroll
    for (int o = 16; o > 0; o >>= 1) ss += __shfl_xor_sync(0xffffffffu, ss, o);
    if ((threadIdx.x & 31) == 0) sm[threadIdx.x >> 5] = ss;
    __syncthreads();
    const float var  = (sm[0]+sm[1]+sm[2]+sm[3]+sm[4]+sm[5]+sm[6]+sm[7]) * (1.f/HH);
    const float rstd = rsqrtf(var + 1e-5f);

    float4 xv = *(const float4*)&x[off];
    float4 gv = *(const float4*)&gamma[c];
    float4 bv = *(const float4*)&beta[c];
    float4 o4;
    o4.x = dx * rstd * gv.x + bv.x + xv.x;
    o4.y = dy * rstd * gv.y + bv.y + xv.y;
    o4.z = dz * rstd * gv.z + bv.z + xv.z;
    o4.w = dw * rstd * gv.w + bv.w + xv.w;
    *(float4*)&out[off] = o4;
}

// ---------------------------------------------------------------------------
extern "C" void kernel_launch(void* const* d_in, const int* in_sizes, int n_in,
                              void* d_out, int out_size)
{
    const float* x     = (const float*)d_in[0];
    const float* Wz    = (const float*)d_in[1];
    const float* bz    = (const float*)d_in[2];
    const float* Wh    = (const float*)d_in[3];
    const float* bh    = (const float*)d_in[4];
    const float* gamma = (const float*)d_in[5];
    const float* beta  = (const float*)d_in[6];
    float* out = (float*)d_out;

    float* hidden = nullptr;
    if ((long long)out_size >= (long long)MM * HH + (long long)BB * HH)
        hidden = out + (size_t)MM * HH;

    static bool attr_set = false;
    if (!attr_set) {
        cudaFuncSetAttribute(gemm_kernel, cudaFuncAttributeMaxDynamicSharedMemorySize, SMEM_BYTES);
        attr_set = true;
    }

    prep_x_kernel<<<(MM * DD / 4) / 256, 256>>>(x);
    prep_w_kernel<<<dim3(DD/32, HH/32), dim3(32, 8)>>>(Wz, 0);
    prep_w_kernel<<<dim3(DD/32, HH/32), dim3(32, 8)>>>(Wh, 1);
    gemm_kernel<<<dim3(HH/64, MM/CTA_M), 256, SMEM_BYTES>>>(bz, bh);
    scan_summary_kernel<<<dim3(HH/128, NCHUNK, BB), 128>>>();
    scan_prefix_kernel<<<(BB*HH)/256, 256>>>(hidden);
    scan_final_kernel<<<dim3(HH/128, NCHUNK, BB), 128>>>();
    ln_residual_kernel<<<MM, 256>>>(x, gamma, beta, out);
}

// round 13
// speedup vs baseline: 1.1593x; 1.0825x over previous
#include <cuda_runtime.h>
#include <cuda_fp16.h>
#include <cstdint>

#define BB 8
#define TT 4096
#define DD 1024
#define HH 1024
#define MM (BB*TT)          // 32768 rows
#define NCHUNK 16
#define CHLEN (TT/NCHUNK)   // 256

// GEMM tiling: CTA 128(M) x 128(N = 64 z-cols + 64 h-cols), 8 warps (64x32 each)
// 2 CTAs per SM (smem 110.6KB each) for inter-CTA tensor-pipe overlap.
#define CTA_M 128
#define KCH 64
#define NKT (DD/KCH)        // 16
#define STAGES 3
#define ROWB 144                                // 128B data + 16B pad
#define A_BYTES (CTA_M*ROWB)                    // 18432
#define B_BYTES (128*ROWB)                      // 18432
#define STAGE_BYTES (A_BYTES + B_BYTES)         // 36864
#define SMEM_BYTES (STAGES*STAGE_BYTES)         // 110592
#define EPI_STRIDE 132

// ---------------- scratch ---------------------------------------------------
__device__ __half g_X16[(size_t)MM*DD];          // x in fp16
__device__ __half g_WH [(size_t)2048*DD];        // interleaved [Wz^T|Wh^T] fp16
__device__ float2 g_ZV[(size_t)MM*HH];           // {1-z, z*g}
__device__ float  g_H [(size_t)MM*HH];
__device__ float  g_SA[BB*NCHUNK*HH];
__device__ float  g_SB[BB*NCHUNK*HH];
__device__ float  g_P [BB*NCHUNK*HH];

// ---------------- helpers ---------------------------------------------------
__device__ __forceinline__ void cp16(void* dst, const void* src) {
    uint32_t d = (uint32_t)__cvta_generic_to_shared(dst);
    asm volatile("cp.async.cg.shared.global [%0], [%1], 16;" :: "r"(d), "l"(src));
}
__device__ __forceinline__ void cp_commit() { asm volatile("cp.async.commit_group;"); }

__device__ __forceinline__ void mma16816(float* c, uint32_t a0, uint32_t a1,
                                         uint32_t a2, uint32_t a3,
                                         uint32_t b0, uint32_t b1) {
    asm volatile("mma.sync.aligned.m16n8k16.row.col.f32.f16.f16.f32 "
                 "{%0,%1,%2,%3}, {%4,%5,%6,%7}, {%8,%9}, {%0,%1,%2,%3};\n"
                 : "+f"(c[0]), "+f"(c[1]), "+f"(c[2]), "+f"(c[3])
                 : "r"(a0), "r"(a1), "r"(a2), "r"(a3), "r"(b0), "r"(b1));
}
__device__ __forceinline__ void ldsm4(uint32_t& r0, uint32_t& r1, uint32_t& r2,
                                      uint32_t& r3, uint32_t saddr) {
    asm volatile("ldmatrix.sync.aligned.m8n8.x4.shared.b16 {%0,%1,%2,%3}, [%4];"
                 : "=r"(r0), "=r"(r1), "=r"(r2), "=r"(r3) : "r"(saddr));
}

// ---------------- prep: x -> fp16 -------------------------------------------
__global__ __launch_bounds__(256)
void prep_x_kernel(const float* __restrict__ x) {
    size_t i = (size_t)blockIdx.x * blockDim.x + threadIdx.x;   // one float4
    float4 v = ((const float4*)x)[i];
    ((__half2*)g_X16)[2*i]   = __half2(__float2half(v.x), __float2half(v.y));
    ((__half2*)g_X16)[2*i+1] = __half2(__float2half(v.z), __float2half(v.w));
}

// ---------------- prep: W[k][h] -> interleaved WT rows ----------------------
__global__ __launch_bounds__(256)
void prep_w_kernel(const float* __restrict__ W, int is_h) {
    __shared__ float tile[32][33];
    const int k0 = blockIdx.x * 32, h0 = blockIdx.y * 32;
    #pragma unroll
    for (int j = 0; j < 4; j++) {
        int kk = threadIdx.y * 4 + j;
        tile[kk][threadIdx.x] = W[(size_t)(k0 + kk) * HH + h0 + threadIdx.x];
    }
    __syncthreads();
    #pragma unroll
    for (int j = 0; j < 4; j++) {
        int h = h0 + threadIdx.y * 4 + j;
        float val = tile[threadIdx.x][threadIdx.y * 4 + j];
        int orow = (h >> 6) * 128 + (is_h ? 64 : 0) + (h & 63);
        g_WH[(size_t)orow * DD + k0 + threadIdx.x] = __float2half(val);
    }
}

// ---------------- GEMM: 128x128 CTA, 2 CTAs/SM, R5-proven pipeline ----------
__device__ __forceinline__ void load_stage(char* smem, int s, int kt, int m0, int nb, int tid) {
    char* stg = smem + s * STAGE_BYTES;
    const int k0 = kt * KCH;
    const __half* gA = g_X16 + (size_t)m0 * DD + k0;
    const __half* gB = g_WH + (size_t)nb * 128 * DD + k0;
    #pragma unroll
    for (int i = 0; i < 8; i++) {
        int q = tid + i * 256;          // 0..2047
        if (q < 1024) {                 // A: 128 rows x 8 chunks
            int row = q >> 3, c = q & 7;
            cp16(stg + row * ROWB + c * 16, gA + (size_t)row * DD + c * 8);
        } else {                        // B: 128 rows x 8 chunks
            int q2 = q - 1024, row = q2 >> 3, c = q2 & 7;
            cp16(stg + A_BYTES + row * ROWB + c * 16, gB + (size_t)row * DD + c * 8);
        }
    }
}

__global__ __launch_bounds__(256, 2)
void gemm_kernel(const float* __restrict__ bz, const float* __restrict__ bh) {
    extern __shared__ char smem[];
    const int tid  = threadIdx.x;
    const int wid  = tid >> 5;
    const int lane = tid & 31;
    const int wm = wid >> 2;            // 0..1 -> M offset wm*64
    const int wn = wid & 3;             // 0..3 -> B-row offset wn*32
    const int nb = blockIdx.x;          // 0..15
    const int m0 = blockIdx.y * CTA_M;
    const int h0 = nb * 64;

    const uint32_t sbase = (uint32_t)__cvta_generic_to_shared(smem);

    float acc[4][4][4];
    #pragma unroll
    for (int mi = 0; mi < 4; mi++)
        #pragma unroll
        for (int ni = 0; ni < 4; ni++)
            #pragma unroll
            for (int j = 0; j < 4; j++) acc[mi][ni][j] = 0.f;

    #pragma unroll
    for (int s = 0; s < STAGES - 1; s++) { load_stage(smem, s, s, m0, nb, tid); cp_commit(); }

    // LDSM lane addressing (R4-proven for 64x32 warp tile)
    const int g = lane >> 3, l = lane & 7;
    const uint32_t aoff = (uint32_t)((wm * 64 + (g & 1) * 8 + l) * ROWB + (g >> 1) * 16);
    const uint32_t boff = (uint32_t)((wn * 32 + (g >> 1) * 8 + l) * ROWB + (g & 1) * 16);

    uint32_t af[2][4][4];   // [buf][mi][frag]
    uint32_t bf[2][4][2];   // [buf][ni][frag]

    #pragma unroll 1
    for (int kt = 0; kt < NKT; kt++) {
        asm volatile("cp.async.wait_group 1;" ::: "memory");
        __syncthreads();
        if (kt + STAGES - 1 < NKT)
            load_stage(smem, (kt + STAGES - 1) % STAGES, kt + STAGES - 1, m0, nb, tid);
        cp_commit();

        const uint32_t stg = sbase + (kt % STAGES) * STAGE_BYTES;
        const uint32_t Ab = stg + aoff;
        const uint32_t Bb = stg + A_BYTES + boff;

        // preload kk=0 fragments
        #pragma unroll
        for (int mi = 0; mi < 4; mi++)
            ldsm4(af[0][mi][0], af[0][mi][1], af[0][mi][2], af[0][mi][3],
                  Ab + mi * 16 * ROWB);
        #pragma unroll
        for (int p = 0; p < 2; p++)
            ldsm4(bf[0][2*p][0], bf[0][2*p][1], bf[0][2*p+1][0], bf[0][2*p+1][1],
                  Bb + p * 16 * ROWB);

        #pragma unroll
        for (int kk = 0; kk < 4; kk++) {
            const int cur = kk & 1, nxt = cur ^ 1;
            if (kk < 3) {
                const uint32_t kb = (kk + 1) * 32;
                #pragma unroll
                for (int mi = 0; mi < 4; mi++)
                    ldsm4(af[nxt][mi][0], af[nxt][mi][1], af[nxt][mi][2], af[nxt][mi][3],
                          Ab + kb + mi * 16 * ROWB);
                #pragma unroll
                for (int p = 0; p < 2; p++)
                    ldsm4(bf[nxt][2*p][0], bf[nxt][2*p][1], bf[nxt][2*p+1][0], bf[nxt][2*p+1][1],
                          Bb + kb + p * 16 * ROWB);
            }
            #pragma unroll
            for (int mi = 0; mi < 4; mi++)
                #pragma unroll
                for (int ni = 0; ni < 4; ni++)
                    mma16816(acc[mi][ni], af[cur][mi][0], af[cur][mi][1],
                             af[cur][mi][2], af[cur][mi][3],
                             bf[cur][ni][0], bf[cur][ni][1]);
        }
        __syncthreads();
    }
    asm volatile("cp.async.wait_group 0;" ::: "memory");
    __syncthreads();

    // ---- epilogue: stage accums through smem, fuse activations ----
    float* epi = (float*)smem;   // [128][EPI_STRIDE]
    #pragma unroll
    for (int mi = 0; mi < 4; mi++) {
        #pragma unroll
        for (int ni = 0; ni < 4; ni++) {
            int r0 = wm * 64 + mi * 16 + (lane >> 2);
            int c0 = wn * 32 + ni * 8 + (lane & 3) * 2;
            *(float2*)&epi[(size_t)r0 * EPI_STRIDE + c0] = make_float2(acc[mi][ni][0], acc[mi][ni][1]);
            *(float2*)&epi[(size_t)(r0 + 8) * EPI_STRIDE + c0] = make_float2(acc[mi][ni][2], acc[mi][ni][3]);
        }
    }
    __syncthreads();

    const int r = tid >> 1;              // 0..127
    const int cb = (tid & 1) * 32;       // 0 or 32
    const size_t zvbase = (size_t)(m0 + r) * HH + h0 + cb;
    #pragma unroll 4
    for (int c = 0; c < 32; c += 2) {
        float k0v = epi[(size_t)r * EPI_STRIDE + cb + c]     + __ldg(&bz[h0 + cb + c]);
        float k1v = epi[(size_t)r * EPI_STRIDE + cb + c + 1] + __ldg(&bz[h0 + cb + c + 1]);
        float a0v = epi[(size_t)r * EPI_STRIDE + 64 + cb + c]     + __ldg(&bh[h0 + cb + c]);
        float a1v = epi[(size_t)r * EPI_STRIDE + 64 + cb + c + 1] + __ldg(&bh[h0 + cb + c + 1]);
        float e0 = __expf(-k0v), e1 = __expf(-k1v);
        float i0 = __fdividef(1.f, 1.f + e0), i1 = __fdividef(1.f, 1.f + e1);
        float om0 = e0 * i0, om1 = e1 * i1;           // 1 - z
        float g0 = (a0v >= 0.f) ? (a0v + 0.5f) : __fdividef(1.f, 1.f + __expf(-a0v));
        float g1 = (a1v >= 0.f) ? (a1v + 0.5f) : __fdividef(1.f, 1.f + __expf(-a1v));
        *(float4*)&g_ZV[zvbase + c] = make_float4(om0, i0 * g0, om1, i1 * g1);
    }
}

// ---------------- scan kernels ---------------------------------------------
__global__ __launch_bounds__(128)
void scan_summary_kernel() {
    const int ch = blockIdx.x * 128 + threadIdx.x;
    const int c  = blockIdx.y;
    const int b  = blockIdx.z;
    size_t base = ((size_t)b * TT + (size_t)c * CHLEN) * HH + ch;
    float Aacc = 1.f, Bacc = 0.f;
    #pragma unroll 8
    for (int t = 0; t < CHLEN; ++t) {
        const float2 zv = __ldg(&g_ZV[base]);
        Aacc *= zv.x;
        Bacc = fmaf(zv.x, Bacc, zv.y);
        base += HH;
    }
    const int s = (b * NCHUNK + c) * HH + ch;
    g_SA[s] = Aacc;
    g_SB[s] = Bacc;
}

__global__ __launch_bounds__(256)
void scan_prefix_kernel(float* __restrict__ hidden) {
    const int idx = blockIdx.x * blockDim.x + threadIdx.x;
    const int b  = idx / HH;
    const int ch = idx - b * HH;
    float h = 0.f;
    #pragma unroll
    for (int c = 0; c < NCHUNK; ++c) {
        const int s = (b * NCHUNK + c) * HH + ch;
        g_P[s] = h;
        h = fmaf(g_SA[s], h, g_SB[s]);
    }
    if (hidden) hidden[(size_t)b * HH + ch] = h;
}

__global__ __launch_bounds__(128)
void scan_final_kernel() {
    const int ch = blockIdx.x * 128 + threadIdx.x;
    const int c  = blockIdx.y;
    const int b  = blockIdx.z;
    size_t base = ((size_t)b * TT + (size_t)c * CHLEN) * HH + ch;
    float h = g_P[(b * NCHUNK + c) * HH + ch];
    #pragma unroll 8
    for (int t = 0; t < CHLEN; ++t) {
        const float2 zv = __ldg(&g_ZV[base]);
        h = fmaf(zv.x, h, zv.y);
        g_H[base] = h;
        base += HH;
    }
}

// ---------------- LayerNorm + residual -------------------------------------
__global__ __launch_bounds__(256)
void ln_residual_kernel(const float* __restrict__ x,
                        const float* __restrict__ gamma,
                        const float* __restrict__ beta,
                        float* __restrict__ out)
{
    __shared__ float sm[8];
    const int row = blockIdx.x;
    const int c   = threadIdx.x * 4;
    const size_t off = (size_t)row * HH + c;

    float4 h4 = *(const float4*)&g_H[off];
    float s = h4.x + h4.y + h4.z + h4.w;
    #pragma unroll
    for (int o = 16; o > 0; o >>= 1) s += __shfl_xor_sync(0xffffffffu, s, o);
    if ((threadIdx.x & 31) == 0) sm[threadIdx.x >> 5] = s;
    __syncthreads();
    const float mean = (sm[0]+sm[1]+sm[2]+sm[3]+sm[4]+sm[5]+sm[6]+sm[7]) * (1.f/HH);
    __syncthreads();

    const float dx = h4.x - mean, dy = h4.y - mean, dz = h4.z - mean, dw = h4.w - mean;
    float ss = dx*dx + dy*dy + dz*dz + dw*dw;
    #pragma unroll
    for (int o = 16; o > 0; o >>= 1) ss += __shfl_xor_sync(0xffffffffu, ss, o);
    if ((threadIdx.x & 31) == 0) sm[threadIdx.x >> 5] = ss;
    __syncthreads();
    const float var  = (sm[0]+sm[1]+sm[2]+sm[3]+sm[4]+sm[5]+sm[6]+sm[7]) * (1.f/HH);
    const float rstd = rsqrtf(var + 1e-5f);

    float4 xv = *(const float4*)&x[off];
    float4 gv = *(const float4*)&gamma[c];
    float4 bv = *(const float4*)&beta[c];
    float4 o4;
    o4.x = dx * rstd * gv.x + bv.x + xv.x;
    o4.y = dy * rstd * gv.y + bv.y + xv.y;
    o4.z = dz * rstd * gv.z + bv.z + xv.z;
    o4.w = dw * rstd * gv.w + bv.w + xv.w;
    *(float4*)&out[off] = o4;
}

// ---------------------------------------------------------------------------
extern "C" void kernel_launch(void* const* d_in, const int* in_sizes, int n_in,
                              void* d_out, int out_size)
{
    const float* x     = (const float*)d_in[0];
    const float* Wz    = (const float*)d_in[1];
    const float* bz    = (const float*)d_in[2];
    const float* Wh    = (const float*)d_in[3];
    const float* bh    = (const float*)d_in[4];
    const float* gamma = (const float*)d_in[5];
    const float* beta  = (const float*)d_in[6];
    float* out = (float*)d_out;

    float* hidden = nullptr;
    if ((long long)out_size >= (long long)MM * HH + (long long)BB * HH)
        hidden = out + (size_t)MM * HH;

    static bool attr_set = false;
    if (!attr_set) {
        cudaFuncSetAttribute(gemm_kernel, cudaFuncAttributeMaxDynamicSharedMemorySize, SMEM_BYTES);
        attr_set = true;
    }

    prep_x_kernel<<<(MM * DD / 4) / 256, 256>>>(x);
    prep_w_kernel<<<dim3(DD/32, HH/32), dim3(32, 8)>>>(Wz, 0);
    prep_w_kernel<<<dim3(DD/32, HH/32), dim3(32, 8)>>>(Wh, 1);
    gemm_kernel<<<dim3(HH/64, MM/CTA_M), 256, SMEM_BYTES>>>(bz, bh);
    scan_summary_kernel<<<dim3(HH/128, NCHUNK, BB), 128>>>();
    scan_prefix_kernel<<<(BB*HH)/256, 256>>>(hidden);
    scan_final_kernel<<<dim3(HH/128, NCHUNK, BB), 128>>>();
    ln_residual_kernel<<<MM, 256>>>(x, gamma, beta, out);
}

// round 14
// speedup vs baseline: 1.3158x; 1.1350x over previous
#include <cuda_runtime.h>
#include <cuda_fp16.h>
#include <cstdint>

#define BB 8
#define TT 4096
#define DD 1024
#define HH 1024
#define MM (BB*TT)          // 32768 rows
#define NCHUNK 16
#define CHLEN (TT/NCHUNK)   // 256

// GEMM tiling: CTA 128(M) x 128(N = 64 z + 64 h cols), 4 warps of 64x64.
// 2 CTAs per SM; crossbar:tensor ratio 0.77 per CTA + inter-CTA overlap.
#define CTA_M 128
#define KCH 64
#define NKT (DD/KCH)        // 16
#define STAGES 3
#define ROWB 144                                // 128B data + 16B pad
#define A_BYTES (CTA_M*ROWB)                    // 18432
#define B_BYTES (128*ROWB)                      // 18432
#define STAGE_BYTES (A_BYTES + B_BYTES)         // 36864
#define SMEM_BYTES (STAGES*STAGE_BYTES)         // 110592
#define EPI_STRIDE 132

// ---------------- scratch ---------------------------------------------------
__device__ __half  g_X16[(size_t)MM*DD];         // x in fp16
__device__ __half  g_WH [(size_t)2048*DD];       // interleaved [Wz^T|Wh^T] fp16
__device__ __half2 g_ZV[(size_t)MM*HH];          // {1-z, v} fp16 packed
__device__ float   g_H [(size_t)MM*HH];
__device__ float   g_SA[BB*NCHUNK*HH];
__device__ float   g_SB[BB*NCHUNK*HH];
__device__ float   g_P [BB*NCHUNK*HH];

// ---------------- helpers ---------------------------------------------------
__device__ __forceinline__ void cp16(void* dst, const void* src) {
    uint32_t d = (uint32_t)__cvta_generic_to_shared(dst);
    asm volatile("cp.async.cg.shared.global [%0], [%1], 16;" :: "r"(d), "l"(src));
}
__device__ __forceinline__ void cp_commit() { asm volatile("cp.async.commit_group;"); }

__device__ __forceinline__ void mma16816(float* c, uint32_t a0, uint32_t a1,
                                         uint32_t a2, uint32_t a3,
                                         uint32_t b0, uint32_t b1) {
    asm volatile("mma.sync.aligned.m16n8k16.row.col.f32.f16.f16.f32 "
                 "{%0,%1,%2,%3}, {%4,%5,%6,%7}, {%8,%9}, {%0,%1,%2,%3};\n"
                 : "+f"(c[0]), "+f"(c[1]), "+f"(c[2]), "+f"(c[3])
                 : "r"(a0), "r"(a1), "r"(a2), "r"(a3), "r"(b0), "r"(b1));
}
__device__ __forceinline__ void ldsm4(uint32_t& r0, uint32_t& r1, uint32_t& r2,
                                      uint32_t& r3, uint32_t saddr) {
    asm volatile("ldmatrix.sync.aligned.m8n8.x4.shared.b16 {%0,%1,%2,%3}, [%4];"
                 : "=r"(r0), "=r"(r1), "=r"(r2), "=r"(r3) : "r"(saddr));
}

// ---------------- prep: x -> fp16 -------------------------------------------
__global__ __launch_bounds__(256)
void prep_x_kernel(const float* __restrict__ x) {
    size_t i = (size_t)blockIdx.x * blockDim.x + threadIdx.x;   // one float4
    float4 v = ((const float4*)x)[i];
    ((__half2*)g_X16)[2*i]   = __half2(__float2half(v.x), __float2half(v.y));
    ((__half2*)g_X16)[2*i+1] = __half2(__float2half(v.z), __float2half(v.w));
}

// ---------------- prep: W[k][h] -> interleaved WT rows ----------------------
__global__ __launch_bounds__(256)
void prep_w_kernel(const float* __restrict__ W, int is_h) {
    __shared__ float tile[32][33];
    const int k0 = blockIdx.x * 32, h0 = blockIdx.y * 32;
    #pragma unroll
    for (int j = 0; j < 4; j++) {
        int kk = threadIdx.y * 4 + j;
        tile[kk][threadIdx.x] = W[(size_t)(k0 + kk) * HH + h0 + threadIdx.x];
    }
    __syncthreads();
    #pragma unroll
    for (int j = 0; j < 4; j++) {
        int h = h0 + threadIdx.y * 4 + j;
        float val = tile[threadIdx.x][threadIdx.y * 4 + j];
        int orow = (h >> 6) * 128 + (is_h ? 64 : 0) + (h & 63);
        g_WH[(size_t)orow * DD + k0 + threadIdx.x] = __float2half(val);
    }
}

// ---------------- GEMM: 128x128 CTA, 4 warps 64x64, 2 CTAs/SM ---------------
__device__ __forceinline__ void load_stage(char* smem, int s, int kt, int m0, int nb, int tid) {
    char* stg = smem + s * STAGE_BYTES;
    const int k0 = kt * KCH;
    const __half* gA = g_X16 + (size_t)m0 * DD + k0;
    const __half* gB = g_WH + (size_t)nb * 128 * DD + k0;
    #pragma unroll
    for (int i = 0; i < 16; i++) {
        int q = tid + i * 128;          // 0..2047
        if (q < 1024) {                 // A: 128 rows x 8 chunks
            int row = q >> 3, c = q & 7;
            cp16(stg + row * ROWB + c * 16, gA + (size_t)row * DD + c * 8);
        } else {                        // B: 128 rows x 8 chunks
            int q2 = q - 1024, row = q2 >> 3, c = q2 & 7;
            cp16(stg + A_BYTES + row * ROWB + c * 16, gB + (size_t)row * DD + c * 8);
        }
    }
}

__global__ __launch_bounds__(128, 2)
void gemm_kernel(const float* __restrict__ bz, const float* __restrict__ bh) {
    extern __shared__ char smem[];
    const int tid  = threadIdx.x;
    const int wid  = tid >> 5;
    const int lane = tid & 31;
    const int wm = wid >> 1;            // 0..1 -> M offset wm*64
    const int wn = wid & 1;             // 0..1 -> B-row offset wn*64
    const int nb = blockIdx.x;          // 0..15
    const int m0 = blockIdx.y * CTA_M;
    const int h0 = nb * 64;

    const uint32_t sbase = (uint32_t)__cvta_generic_to_shared(smem);

    float acc[4][8][4];
    #pragma unroll
    for (int mi = 0; mi < 4; mi++)
        #pragma unroll
        for (int ni = 0; ni < 8; ni++)
            #pragma unroll
            for (int j = 0; j < 4; j++) acc[mi][ni][j] = 0.f;

    #pragma unroll
    for (int s = 0; s < STAGES - 1; s++) { load_stage(smem, s, s, m0, nb, tid); cp_commit(); }

    // LDSM lane addressing (R5-proven 64x64 warp tile)
    const int g = lane >> 3, l = lane & 7;
    const uint32_t aoff = (uint32_t)((wm * 64 + (g & 1) * 8 + l) * ROWB + (g >> 1) * 16);
    const uint32_t boff = (uint32_t)((wn * 64 + (g >> 1) * 8 + l) * ROWB + (g & 1) * 16);

    uint32_t af[2][4][4];   // [buf][mi][frag]
    uint32_t bf[2][8][2];   // [buf][ni][frag]

    #pragma unroll 1
    for (int kt = 0; kt < NKT; kt++) {
        asm volatile("cp.async.wait_group 1;" ::: "memory");
        __syncthreads();
        if (kt + STAGES - 1 < NKT)
            load_stage(smem, (kt + STAGES - 1) % STAGES, kt + STAGES - 1, m0, nb, tid);
        cp_commit();

        const uint32_t stg = sbase + (kt % STAGES) * STAGE_BYTES;
        const uint32_t Ab = stg + aoff;
        const uint32_t Bb = stg + A_BYTES + boff;

        // preload kk=0 fragments
        #pragma unroll
        for (int mi = 0; mi < 4; mi++)
            ldsm4(af[0][mi][0], af[0][mi][1], af[0][mi][2], af[0][mi][3],
                  Ab + mi * 16 * ROWB);
        #pragma unroll
        for (int p = 0; p < 4; p++)
            ldsm4(bf[0][2*p][0], bf[0][2*p][1], bf[0][2*p+1][0], bf[0][2*p+1][1],
                  Bb + p * 16 * ROWB);

        #pragma unroll
        for (int kk = 0; kk < 4; kk++) {
            const int cur = kk & 1, nxt = cur ^ 1;
            if (kk < 3) {
                const uint32_t kb = (kk + 1) * 32;
                #pragma unroll
                for (int mi = 0; mi < 4; mi++)
                    ldsm4(af[nxt][mi][0], af[nxt][mi][1], af[nxt][mi][2], af[nxt][mi][3],
                          Ab + kb + mi * 16 * ROWB);
                #pragma unroll
                for (int p = 0; p < 4; p++)
                    ldsm4(bf[nxt][2*p][0], bf[nxt][2*p][1], bf[nxt][2*p+1][0], bf[nxt][2*p+1][1],
                          Bb + kb + p * 16 * ROWB);
            }
            #pragma unroll
            for (int mi = 0; mi < 4; mi++)
                #pragma unroll
                for (int ni = 0; ni < 8; ni++)
                    mma16816(acc[mi][ni], af[cur][mi][0], af[cur][mi][1],
                             af[cur][mi][2], af[cur][mi][3],
                             bf[cur][ni][0], bf[cur][ni][1]);
        }
        __syncthreads();
    }
    asm volatile("cp.async.wait_group 0;" ::: "memory");
    __syncthreads();

    // ---- epilogue: stage accums through smem, fuse activations ----
    float* epi = (float*)smem;   // [128][EPI_STRIDE] = 67.6KB < SMEM_BYTES
    #pragma unroll
    for (int mi = 0; mi < 4; mi++) {
        #pragma unroll
        for (int ni = 0; ni < 8; ni++) {
            int r0 = wm * 64 + mi * 16 + (lane >> 2);
            int c0 = wn * 64 + ni * 8 + (lane & 3) * 2;
            *(float2*)&epi[(size_t)r0 * EPI_STRIDE + c0] = make_float2(acc[mi][ni][0], acc[mi][ni][1]);
            *(float2*)&epi[(size_t)(r0 + 8) * EPI_STRIDE + c0] = make_float2(acc[mi][ni][2], acc[mi][ni][3]);
        }
    }
    __syncthreads();

    const int r = tid;   // 0..127, one row each
    const size_t zvbase = (size_t)(m0 + r) * HH + h0;
    #pragma unroll 2
    for (int c = 0; c < 64; c += 4) {
        uint32_t packed[4];
        #pragma unroll
        for (int j = 0; j < 4; j++) {
            float kv = epi[(size_t)r * EPI_STRIDE + c + j]      + __ldg(&bz[h0 + c + j]);
            float av = epi[(size_t)r * EPI_STRIDE + 64 + c + j] + __ldg(&bh[h0 + c + j]);
            float e  = __expf(-kv);
            float iz = __fdividef(1.f, 1.f + e);
            float om = e * iz;                       // 1 - z
            float gg = (av >= 0.f) ? (av + 0.5f) : __fdividef(1.f, 1.f + __expf(-av));
            __half2 hv = __halves2half2(__float2half_rn(om), __float2half_rn(iz * gg));
            packed[j] = *(uint32_t*)&hv;
        }
        *(uint4*)&g_ZV[zvbase + c] = make_uint4(packed[0], packed[1], packed[2], packed[3]);
    }
}

// ---------------- scan kernels (fp16 ZV) ------------------------------------
__global__ __launch_bounds__(128)
void scan_summary_kernel() {
    const int ch = blockIdx.x * 128 + threadIdx.x;
    const int c  = blockIdx.y;
    const int b  = blockIdx.z;
    size_t base = ((size_t)b * TT + (size_t)c * CHLEN) * HH + ch;
    float Aacc = 1.f, Bacc = 0.f;
    #pragma unroll 8
    for (int t = 0; t < CHLEN; ++t) {
        const float2 zv = __half22float2(__ldg(&g_ZV[base]));
        Aacc *= zv.x;
        Bacc = fmaf(zv.x, Bacc, zv.y);
        base += HH;
    }
    const int s = (b * NCHUNK + c) * HH + ch;
    g_SA[s] = Aacc;
    g_SB[s] = Bacc;
}

__global__ __launch_bounds__(256)
void scan_prefix_kernel(float* __restrict__ hidden) {
    const int idx = blockIdx.x * blockDim.x + threadIdx.x;
    const int b  = idx / HH;
    const int ch = idx - b * HH;
    float h = 0.f;
    #pragma unroll
    for (int c = 0; c < NCHUNK; ++c) {
        const int s = (b * NCHUNK + c) * HH + ch;
        g_P[s] = h;
        h = fmaf(g_SA[s], h, g_SB[s]);
    }
    if (hidden) hidden[(size_t)b * HH + ch] = h;
}

__global__ __launch_bounds__(128)
void scan_final_kernel() {
    const int ch = blockIdx.x * 128 + threadIdx.x;
    const int c  = blockIdx.y;
    const int b  = blockIdx.z;
    size_t base = ((size_t)b * TT + (size_t)c * CHLEN) * HH + ch;
    float h = g_P[(b * NCHUNK + c) * HH + ch];
    #pragma unroll 8
    for (int t = 0; t < CHLEN; ++t) {
        const float2 zv = __half22float2(__ldg(&g_ZV[base]));
        h = fmaf(zv.x, h, zv.y);
        g_H[base] = h;
        base += HH;
    }
}

// ---------------- LayerNorm + residual -------------------------------------
__global__ __launch_bounds__(256)
void ln_residual_kernel(const float* __restrict__ x,
                        const float* __restrict__ gamma,
                        const float* __restrict__ beta,
                        float* __restrict__ out)
{
    __shared__ float sm[8];
    const int row = blockIdx.x;
    const int c   = threadIdx.x * 4;
    const size_t off = (size_t)row * HH + c;

    float4 h4 = *(const float4*)&g_H[off];
    float s = h4.x + h4.y + h4.z + h4.w;
    #pragma unroll
    for (int o = 16; o > 0; o >>= 1) s += __shfl_xor_sync(0xffffffffu, s, o);
    if ((threadIdx.x & 31) == 0) sm[threadIdx.x >> 5] = s;
    __syncthreads();
    const float mean = (sm[0]+sm[1]+sm[2]+sm[3]+sm[4]+sm[5]+sm[6]+sm[7]) * (1.f/HH);
    __syncthreads();

    const float dx = h4.x - mean, dy = h4.y - mean, dz = h4.z - mean, dw = h4.w - mean;
    float ss = dx*dx + dy*dy + dz*dz + dw*dw;
    #pragma unroll
    for (int o = 16; o > 0; o >>= 1) ss += __shfl_xor_sync(0xffffffffu, ss, o);
    if ((threadIdx.x & 31) == 0) sm[threadIdx.x >> 5] = ss;
    __syncthreads();
    const float var  = (sm[0]+sm[1]+sm[2]+sm[3]+sm[4]+sm[5]+sm[6]+sm[7]) * (1.f/HH);
    const float rstd = rsqrtf(var + 1e-5f);

    float4 xv = *(const float4*)&x[off];
    float4 gv = *(const float4*)&gamma[c];
    float4 bv = *(const float4*)&beta[c];
    float4 o4;
    o4.x = dx * rstd * gv.x + bv.x + xv.x;
    o4.y = dy * rstd * gv.y + bv.y + xv.y;
    o4.z = dz * rstd * gv.z + bv.z + xv.z;
    o4.w = dw * rstd * gv.w + bv.w + xv.w;
    *(float4*)&out[off] = o4;
}

// ---------------------------------------------------------------------------
extern "C" void kernel_launch(void* const* d_in, const int* in_sizes, int n_in,
                              void* d_out, int out_size)
{
    const float* x     = (const float*)d_in[0];
    const float* Wz    = (const float*)d_in[1];
    const float* bz    = (const float*)d_in[2];
    const float* Wh    = (const float*)d_in[3];
    const float* bh    = (const float*)d_in[4];
    const float* gamma = (const float*)d_in[5];
    const float* beta  = (const float*)d_in[6];
    float* out = (float*)d_out;

    float* hidden = nullptr;
    if ((long long)out_size >= (long long)MM * HH + (long long)BB * HH)
        hidden = out + (size_t)MM * HH;

    static bool attr_set = false;
    if (!attr_set) {
        cudaFuncSetAttribute(gemm_kernel, cudaFuncAttributeMaxDynamicSharedMemorySize, SMEM_BYTES);
        attr_set = true;
    }

    prep_x_kernel<<<(MM * DD / 4) / 256, 256>>>(x);
    prep_w_kernel<<<dim3(DD/32, HH/32), dim3(32, 8)>>>(Wz, 0);
    prep_w_kernel<<<dim3(DD/32, HH/32), dim3(32, 8)>>>(Wh, 1);
    gemm_kernel<<<dim3(HH/64, MM/CTA_M), 128, SMEM_BYTES>>>(bz, bh);
    scan_summary_kernel<<<dim3(HH/128, NCHUNK, BB), 128>>>();
    scan_prefix_kernel<<<(BB*HH)/256, 256>>>(hidden);
    scan_final_kernel<<<dim3(HH/128, NCHUNK, BB), 128>>>();
    ln_residual_kernel<<<MM, 256>>>(x, gamma, beta, out);
}